// round 6
// baseline (speedup 1.0000x reference)
#include <cuda_runtime.h>

// PairDistanceLoss: loss_i = (sum_{y=1} e^x)(sum_{y=0} e^{-x}) / (ni*(C-ni)); out = mean_i loss_i
// Shapes fixed: N=16384 rows, C=4096 cols. x: float32. y: int32 (JAX x64 disabled
// silently downcasts the reference's "int64" randint to int32). out: float32 scalar.

#define NROWS 16384
#define CCOLS 4096
#define BLK   256

// Scratch: per-row loss (fully overwritten every launch; no init needed).
__device__ float g_rowloss[NROWS];

__device__ __forceinline__ void acc_elem(float xv, int yv,
                                         float& pos, float& neg, int& ni) {
    bool p = (yv != 0);
    float e = __expf(p ? xv : -xv);
    pos += p ? e : 0.0f;
    neg += p ? 0.0f : e;
    ni  += p ? 1 : 0;
}

__global__ __launch_bounds__(BLK, 1)
void pdl_row_kernel(const float* __restrict__ x, const int* __restrict__ y) {
    const int row = blockIdx.x;
    const size_t base = (size_t)row * CCOLS;
    const float4* x4 = reinterpret_cast<const float4*>(x + base);
    const int4*   y4 = reinterpret_cast<const int4*>(y + base);

    const int tid = threadIdx.x;
    float pos = 0.0f, neg = 0.0f;
    int ni = 0;

    // C/4 = 1024 vec4 per row; 256 threads -> 4 fully-unrolled iterations.
    // Per iter: one 16B x load + one 16B y load, fully coalesced, 8 loads in flight.
#pragma unroll
    for (int i = 0; i < 4; ++i) {
        const int idx = tid + i * BLK;   // vec4 index 0..1023
        float4 xv = x4[idx];
        int4   yv = y4[idx];
        acc_elem(xv.x, yv.x, pos, neg, ni);
        acc_elem(xv.y, yv.y, pos, neg, ni);
        acc_elem(xv.z, yv.z, pos, neg, ni);
        acc_elem(xv.w, yv.w, pos, neg, ni);
    }

    // Warp reduction
#pragma unroll
    for (int m = 16; m > 0; m >>= 1) {
        pos += __shfl_xor_sync(0xFFFFFFFFu, pos, m);
        neg += __shfl_xor_sync(0xFFFFFFFFu, neg, m);
        ni  += __shfl_xor_sync(0xFFFFFFFFu, ni,  m);
    }

    // Block reduction across 8 warps
    __shared__ float s_pos[8], s_neg[8];
    __shared__ int   s_ni[8];
    const int wid = tid >> 5, lid = tid & 31;
    if (lid == 0) { s_pos[wid] = pos; s_neg[wid] = neg; s_ni[wid] = ni; }
    __syncthreads();

    if (wid == 0) {
        float p8 = (lid < 8) ? s_pos[lid] : 0.0f;
        float n8 = (lid < 8) ? s_neg[lid] : 0.0f;
        int   c8 = (lid < 8) ? s_ni[lid]  : 0;
#pragma unroll
        for (int m = 4; m > 0; m >>= 1) {
            p8 += __shfl_xor_sync(0xFFFFFFFFu, p8, m);
            n8 += __shfl_xor_sync(0xFFFFFFFFu, n8, m);
            c8 += __shfl_xor_sync(0xFFFFFFFFu, c8, m);
        }
        if (lid == 0) {
            float denom = (float)c8 * (float)(CCOLS - c8);
            g_rowloss[row] = p8 * n8 / denom;
        }
    }
}

__global__ __launch_bounds__(BLK, 1)
void pdl_reduce_kernel(float* __restrict__ out) {
    __shared__ double sh[BLK];
    const int tid = threadIdx.x;
    double s = 0.0;
    for (int i = tid; i < NROWS; i += BLK)
        s += (double)g_rowloss[i];
    sh[tid] = s;
    __syncthreads();
#pragma unroll
    for (int k = BLK / 2; k > 0; k >>= 1) {
        if (tid < k) sh[tid] += sh[tid + k];
        __syncthreads();
    }
    if (tid == 0)
        out[0] = (float)(sh[0] / (double)NROWS);
}

extern "C" void kernel_launch(void* const* d_in, const int* in_sizes, int n_in,
                              void* d_out, int out_size) {
    const float* x = (const float*)d_in[0];
    const int*   y = (const int*)d_in[1];
    float* out = (float*)d_out;

    pdl_row_kernel<<<NROWS, BLK>>>(x, y);
    pdl_reduce_kernel<<<1, BLK>>>(out);
}

// round 8
// speedup vs baseline: 1.2569x; 1.2569x over previous
#include <cuda_runtime.h>

// PairDistanceLoss: loss_i = (sum_{y=1} e^x)(sum_{y=0} e^{-x}) / (ni*(C-ni)); out = mean_i loss_i
// Shapes fixed: N=16384 rows, C=4096 cols. x: float32, y: int32, out: float32 scalar.
//
// R6 post-mortem: row kernel already at ~7.0 TB/s (LTS cap); the 21.8us single-block
// reduce kernel was the only waste. Replaced with init-to-zero + one float atomicAdd
// per block (hidden under the memory stream). R7 was a container/infra failure;
// resubmitting the same design.

#define NROWS 16384
#define CCOLS 4096
#define BLK   256

__device__ __forceinline__ void acc_elem(float xv, int yv,
                                         float& pos, float& neg, int& ni) {
    bool p = (yv != 0);
    float e = __expf(p ? xv : -xv);
    pos += p ? e : 0.0f;
    neg += p ? 0.0f : e;
    ni  += p ? 1 : 0;
}

__global__ void pdl_init_kernel(float* __restrict__ out, int n) {
    for (int i = threadIdx.x; i < n; i += blockDim.x)
        out[i] = 0.0f;
}

__global__ __launch_bounds__(BLK, 1)
void pdl_row_kernel(const float* __restrict__ x, const int* __restrict__ y,
                    float* __restrict__ out) {
    const int row = blockIdx.x;
    const size_t base = (size_t)row * CCOLS;
    const float4* x4 = reinterpret_cast<const float4*>(x + base);
    const int4*   y4 = reinterpret_cast<const int4*>(y + base);

    const int tid = threadIdx.x;
    float pos = 0.0f, neg = 0.0f;
    int ni = 0;

    // C/4 = 1024 vec4 per row; 256 threads -> 4 fully-unrolled iterations.
    // Per iter: one 16B x load + one 16B y load, fully coalesced, 8 loads in flight.
#pragma unroll
    for (int i = 0; i < 4; ++i) {
        const int idx = tid + i * BLK;   // vec4 index 0..1023
        float4 xv = x4[idx];
        int4   yv = y4[idx];
        acc_elem(xv.x, yv.x, pos, neg, ni);
        acc_elem(xv.y, yv.y, pos, neg, ni);
        acc_elem(xv.z, yv.z, pos, neg, ni);
        acc_elem(xv.w, yv.w, pos, neg, ni);
    }

    // Warp reduction
#pragma unroll
    for (int m = 16; m > 0; m >>= 1) {
        pos += __shfl_xor_sync(0xFFFFFFFFu, pos, m);
        neg += __shfl_xor_sync(0xFFFFFFFFu, neg, m);
        ni  += __shfl_xor_sync(0xFFFFFFFFu, ni,  m);
    }

    // Block reduction across 8 warps
    __shared__ float s_pos[8], s_neg[8];
    __shared__ int   s_ni[8];
    const int wid = tid >> 5, lid = tid & 31;
    if (lid == 0) { s_pos[wid] = pos; s_neg[wid] = neg; s_ni[wid] = ni; }
    __syncthreads();

    if (wid == 0) {
        float p8 = (lid < 8) ? s_pos[lid] : 0.0f;
        float n8 = (lid < 8) ? s_neg[lid] : 0.0f;
        int   c8 = (lid < 8) ? s_ni[lid]  : 0;
#pragma unroll
        for (int m = 4; m > 0; m >>= 1) {
            p8 += __shfl_xor_sync(0xFFFFFFFFu, p8, m);
            n8 += __shfl_xor_sync(0xFFFFFFFFu, n8, m);
            c8 += __shfl_xor_sync(0xFFFFFFFFu, c8, m);
        }
        if (lid == 0) {
            float denom = (float)c8 * (float)(CCOLS - c8);
            float contrib = p8 * n8 / denom * (1.0f / (float)NROWS);
            atomicAdd(out, contrib);   // RED.ADD.F32, one per block, hidden
        }
    }
}

extern "C" void kernel_launch(void* const* d_in, const int* in_sizes, int n_in,
                              void* d_out, int out_size) {
    const float* x = (const float*)d_in[0];
    const int*   y = (const int*)d_in[1];
    float* out = (float*)d_out;

    pdl_init_kernel<<<1, 32>>>(out, out_size > 0 ? out_size : 1);
    pdl_row_kernel<<<NROWS, BLK>>>(x, y, out);
}

// round 9
// speedup vs baseline: 1.2683x; 1.0090x over previous
#include <cuda_runtime.h>

// PairDistanceLoss: loss_i = (sum_{y=1} e^x)(sum_{y=0} e^{-x}) / (ni*(C-ni)); out = mean_i loss_i
// Shapes fixed: N=16384 rows, C=4096 cols. x: float32, y: int32, out: float32 scalar.
//
// R8 post-mortem: 78.6us total, row kernel 77.6us @ 88% DRAM (6975 GB/s) — HBM-bound,
// prediction matched. R9: fold init into the row kernel via last-block ticket
// (atomicExch reads+resets accumulator in one op; ticket wraps for graph replay),
// and use __ldcs streaming loads (touch-once data, evict-first).

#define NROWS 16384
#define CCOLS 4096
#define BLK   256

// Scratch accumulator + ticket. Zero at module load; the last block of every
// launch resets both (atomicExch / atomicInc-wraparound), so every graph replay
// starts from zero. Allocation-free, deterministic work.
__device__ float        g_acc = 0.0f;
__device__ unsigned int g_ticket = 0u;

__device__ __forceinline__ void acc_elem(float xv, int yv,
                                         float& pos, float& neg, int& ni) {
    bool p = (yv != 0);
    float e = __expf(p ? xv : -xv);
    pos += p ? e : 0.0f;
    neg += p ? 0.0f : e;
    ni  += p ? 1 : 0;
}

__global__ __launch_bounds__(BLK, 1)
void pdl_row_kernel(const float* __restrict__ x, const int* __restrict__ y,
                    float* __restrict__ out) {
    const int row = blockIdx.x;
    const size_t base = (size_t)row * CCOLS;
    const float4* x4 = reinterpret_cast<const float4*>(x + base);
    const int4*   y4 = reinterpret_cast<const int4*>(y + base);

    const int tid = threadIdx.x;
    float pos = 0.0f, neg = 0.0f;
    int ni = 0;

    // C/4 = 1024 vec4 per row; 256 threads -> 4 fully-unrolled iterations.
    // Streaming loads (.cs): touch-once data, evict-first in L1/L2.
#pragma unroll
    for (int i = 0; i < 4; ++i) {
        const int idx = tid + i * BLK;   // vec4 index 0..1023
        float4 xv = __ldcs(&x4[idx]);
        int4   yv = __ldcs(&y4[idx]);
        acc_elem(xv.x, yv.x, pos, neg, ni);
        acc_elem(xv.y, yv.y, pos, neg, ni);
        acc_elem(xv.z, yv.z, pos, neg, ni);
        acc_elem(xv.w, yv.w, pos, neg, ni);
    }

    // Warp reduction
#pragma unroll
    for (int m = 16; m > 0; m >>= 1) {
        pos += __shfl_xor_sync(0xFFFFFFFFu, pos, m);
        neg += __shfl_xor_sync(0xFFFFFFFFu, neg, m);
        ni  += __shfl_xor_sync(0xFFFFFFFFu, ni,  m);
    }

    // Block reduction across 8 warps
    __shared__ float s_pos[8], s_neg[8];
    __shared__ int   s_ni[8];
    const int wid = tid >> 5, lid = tid & 31;
    if (lid == 0) { s_pos[wid] = pos; s_neg[wid] = neg; s_ni[wid] = ni; }
    __syncthreads();

    if (wid == 0 && lid == 0) {
        float p8 = 0.0f, n8 = 0.0f;
        int c8 = 0;
#pragma unroll
        for (int w = 0; w < 8; ++w) { p8 += s_pos[w]; n8 += s_neg[w]; c8 += s_ni[w]; }

        float denom = (float)c8 * (float)(CCOLS - c8);
        float contrib = p8 * n8 / denom * (1.0f / (float)NROWS);
        atomicAdd(&g_acc, contrib);

        // Order this block's accumulator add before its ticket increment.
        __threadfence();

        // atomicInc with val=NROWS-1 wraps to 0 when old==NROWS-1 -> ticket
        // self-resets every launch (graph-replay safe).
        unsigned int old = atomicInc(&g_ticket, NROWS - 1u);
        if (old == NROWS - 1u) {
            // All 16384 contributions are in L2 (ticket observed after their
            // fences). Read total and reset scratch in one atomic op.
            __threadfence();
            float total = atomicExch(&g_acc, 0.0f);
            out[0] = total;
        }
    }
}

extern "C" void kernel_launch(void* const* d_in, const int* in_sizes, int n_in,
                              void* d_out, int out_size) {
    const float* x = (const float*)d_in[0];
    const int*   y = (const int*)d_in[1];
    float* out = (float*)d_out;

    pdl_row_kernel<<<NROWS, BLK>>>(x, y, out);
}